// round 14
// baseline (speedup 1.0000x reference)
#include <cuda_runtime.h>
#include <math_constants.h>

#define NN 50000
#define EE 800000
#define HH 4
#define CC 64
#define DE 16
#define GG 64
#define HC 256   // H*C
#define NEG_SLOPE 0.2f
#define GN_EPS 1e-5f
#define NB 196   // ceil(NN/256) scan blocks

// ---------------- device scratch (no allocations allowed) ----------------
__device__ float    g_x[NN * HC];     // projected node features [N, H*C]  (51.2 MB)
__device__ float    g_asrc[NN * HH];  // per-node src attention logits
__device__ float    g_adst[NN * HH];  // per-node dst attention logits
__device__ float    g_denom[NN * HH]; // segment sum of exp per (dst, h)
__device__ float    g_vedge[DE * HH]; // folded W_edge @ att_edge, layout [d][h]
__device__ unsigned g_cnt[NN];        // in-degree histogram
__device__ unsigned g_rowptr[NN];     // CSR row starts
__device__ unsigned g_cursor[NN];     // scatter cursors
__device__ unsigned g_bsum[256];      // per-block scan totals
__device__ int      g_eid[EE];        // CSR edge ids grouped by dst

__device__ __forceinline__ void red_add_v4(float* p, float a, float b, float c, float d) {
    asm volatile("red.global.add.v4.f32 [%0], {%1, %2, %3, %4};"
                 :: "l"(p), "f"(a), "f"(b), "f"(c), "f"(d) : "memory");
}

// ---------------- kernels ----------------

// Zero softmax denominators and degree histogram.
__global__ void k_init() {
    int i = blockIdx.x * blockDim.x + threadIdx.x;
    int stride = gridDim.x * blockDim.x;
    for (int j = i; j < NN * HH; j += stride) g_denom[j] = 0.0f;
    for (int j = i; j < NN; j += stride) g_cnt[j] = 0u;
}

// v[d][h] = sum_c W_edge[d, h*C + c] * att_edge[h, c]   (tiny: 16x4)
__global__ void k_vedge(const float* __restrict__ We, const float* __restrict__ ae) {
    int t = threadIdx.x;           // 64 threads
    int d = t >> 2, h = t & 3;
    float s = 0.0f;
    #pragma unroll 16
    for (int c = 0; c < CC; c++)
        s = fmaf(We[d * HC + h * CC + c], ae[h * CC + c], s);
    g_vedge[d * HH + h] = s;
}

// x = node @ W, fused with a_src/a_dst reduction (values never leave registers).
#define PROJ_ROWS 32
__global__ void k_proj(const float* __restrict__ node, const float* __restrict__ W,
                       const float* __restrict__ att_src, const float* __restrict__ att_dst) {
    __shared__ float sn[PROJ_ROWS][CC];
    __shared__ float s_s[8][PROJ_ROWS];
    __shared__ float s_d[8][PROJ_ROWS];
    int block0 = blockIdx.x * PROJ_ROWS;
    int tid = threadIdx.x;  // 256
    for (int i = tid; i < PROJ_ROWS * CC; i += 256) {
        int r = i >> 6, c = i & 63;
        int n = block0 + r;
        sn[r][c] = (n < NN) ? node[n * CC + c] : 0.0f;
    }
    __syncthreads();
    float acc[PROJ_ROWS];
    #pragma unroll
    for (int r = 0; r < PROJ_ROWS; r++) acc[r] = 0.0f;
    #pragma unroll 4
    for (int k = 0; k < CC; k++) {
        float wk = W[k * HC + tid];
        #pragma unroll
        for (int r = 0; r < PROJ_ROWS; r++) acc[r] = fmaf(sn[r][k], wk, acc[r]);
    }
    float as = att_src[tid], ad = att_dst[tid];
    int warp = tid >> 5, lane = tid & 31;
    #pragma unroll
    for (int r = 0; r < PROJ_ROWS; r++) {
        int n = block0 + r;
        if (n < NN) g_x[(size_t)n * HC + tid] = acc[r];
        float ps = acc[r] * as;
        float pd = acc[r] * ad;
        #pragma unroll
        for (int o = 16; o > 0; o >>= 1) {
            ps += __shfl_xor_sync(0xffffffffu, ps, o);
            pd += __shfl_xor_sync(0xffffffffu, pd, o);
        }
        if (lane == 0) { s_s[warp][r] = ps; s_d[warp][r] = pd; }
    }
    __syncthreads();
    int r = tid & 31;
    int h = (tid >> 5) & 3;
    int which = tid >> 7;
    int n = block0 + r;
    if (n < NN) {
        if (which == 0) g_asrc[n * HH + h] = s_s[2 * h][r] + s_s[2 * h + 1][r];
        else            g_adst[n * HH + h] = s_d[2 * h][r] + s_d[2 * h + 1][r];
    }
}

// Edge pass: ex = exp(lrelu(a_src[src]+a_dst[dst]+edge_attr@v)) (no max needed:
// logits are O(10), far from fp32 overflow; ratio mathematically identical).
// Stores ex, accumulates denom (one v4 RED), builds in-degree histogram.
__global__ void k_edgeA(const int* __restrict__ ei,
                        const float* __restrict__ edge_attr,
                        float* __restrict__ att) {
    __shared__ float sv[DE * HH];
    if (threadIdx.x < DE * HH) sv[threadIdx.x] = g_vedge[threadIdx.x];
    __syncthreads();
    int e = blockIdx.x * blockDim.x + threadIdx.x;
    if (e >= EE) return;
    const float4* ea = (const float4*)(edge_attr + (size_t)e * DE);
    float aeh[HH] = {0.f, 0.f, 0.f, 0.f};
    #pragma unroll
    for (int q = 0; q < 4; q++) {
        float4 t = ea[q];
        #pragma unroll
        for (int h = 0; h < HH; h++) {
            aeh[h] += t.x * sv[(q * 4 + 0) * HH + h]
                    + t.y * sv[(q * 4 + 1) * HH + h]
                    + t.z * sv[(q * 4 + 2) * HH + h]
                    + t.w * sv[(q * 4 + 3) * HH + h];
        }
    }
    int src = ei[e], dst = ei[EE + e];
    float4 s4 = *(const float4*)(g_asrc + src * HH);
    float4 d4 = *(const float4*)(g_adst + dst * HH);
    float a0 = s4.x + d4.x + aeh[0];
    float a1 = s4.y + d4.y + aeh[1];
    float a2 = s4.z + d4.z + aeh[2];
    float a3 = s4.w + d4.w + aeh[3];
    a0 = (a0 > 0.0f) ? a0 : NEG_SLOPE * a0;
    a1 = (a1 > 0.0f) ? a1 : NEG_SLOPE * a1;
    a2 = (a2 > 0.0f) ? a2 : NEG_SLOPE * a2;
    a3 = (a3 > 0.0f) ? a3 : NEG_SLOPE * a3;
    float e0 = __expf(a0), e1 = __expf(a1), e2 = __expf(a2), e3 = __expf(a3);
    *(float4*)(att + (size_t)e * HH) = make_float4(e0, e1, e2, e3);
    red_add_v4(&g_denom[dst * HH], e0, e1, e2, e3);
    atomicAdd(&g_cnt[dst], 1u);
}

// --- parallel exclusive scan of g_cnt (3 tiny kernels) ---
__global__ void k_scanA() {
    __shared__ unsigned s[256];
    int b = blockIdx.x, tid = threadIdx.x;
    int idx = b * 256 + tid;
    unsigned c = (idx < NN) ? g_cnt[idx] : 0u;
    s[tid] = c;
    __syncthreads();
    unsigned inc = c;
    for (int o = 1; o < 256; o <<= 1) {
        unsigned v = (tid >= o) ? s[tid - o] : 0u;
        __syncthreads();
        s[tid] += v;
        __syncthreads();
    }
    inc = s[tid];
    if (idx < NN) g_rowptr[idx] = inc - c;   // block-local exclusive
    if (tid == 255) g_bsum[b] = inc;         // block total
}
__global__ void k_scanB() {
    __shared__ unsigned s[256];
    int tid = threadIdx.x;
    unsigned c = (tid < NB) ? g_bsum[tid] : 0u;
    s[tid] = c;
    __syncthreads();
    for (int o = 1; o < 256; o <<= 1) {
        unsigned v = (tid >= o) ? s[tid - o] : 0u;
        __syncthreads();
        s[tid] += v;
        __syncthreads();
    }
    g_bsum[tid] = s[tid] - c;                // exclusive block offsets
}
__global__ void k_scanC() {
    int b = blockIdx.x, tid = threadIdx.x;
    int idx = b * 256 + tid;
    if (idx < NN) {
        unsigned r = g_rowptr[idx] + g_bsum[b];
        g_rowptr[idx] = r;
        g_cursor[idx] = r;
    }
}

// Scatter edge ids into dst-grouped CSR order.
__global__ void k_scatter(const int* __restrict__ ei) {
    int e = blockIdx.x * blockDim.x + threadIdx.x;
    if (e >= EE) return;
    int dst = ei[EE + e];
    unsigned pos = atomicAdd(&g_cursor[dst], 1u);
    g_eid[pos] = e;
}

// Gather-aggregate: one warp per dst node, ZERO atomics, deep load pipeline.
// Edge ids + src ids are fetched lane-parallel up front; the channel gather is
// unrolled 4 edges deep so up to 16 independent float2 loads are in flight.
__global__ void __launch_bounds__(256) k_aggr(const int* __restrict__ ei,
                                              float* __restrict__ att,
                                              float* __restrict__ outy) {
    int n = (blockIdx.x * blockDim.x + threadIdx.x) >> 5;
    int lane = threadIdx.x & 31;
    if (n >= NN) return;
    unsigned start = g_rowptr[n];
    unsigned deg = g_cnt[n];
    float4 dn = *(const float4*)(g_denom + n * HH);
    float i0 = 1.0f / (dn.x + 1e-16f);
    float i1 = 1.0f / (dn.y + 1e-16f);
    float i2 = 1.0f / (dn.z + 1e-16f);
    float i3 = 1.0f / (dn.w + 1e-16f);
    float acc0 = 0.0f, acc1 = 0.0f;

    for (unsigned base = 0; base < deg; base += 32) {
        unsigned idx = base + lane;
        int e_l = 0, s_l = 0;
        if (idx < deg) { e_l = g_eid[start + idx]; s_l = ei[e_l]; }
        int m = (int)min(32u, deg - base);
        for (int i = 0; i < m; i += 4) {
            int nj = min(4, m - i);
            int   ee[4];
            int   ss[4];
            float4 ex[4];
            float2 v[4][4];
            #pragma unroll
            for (int j = 0; j < 4; j++) {
                ee[j] = __shfl_sync(0xffffffffu, e_l, i + j);
                ss[j] = __shfl_sync(0xffffffffu, s_l, i + j);
            }
            #pragma unroll
            for (int j = 0; j < 4; j++) {
                if (j < nj) {
                    ex[j] = *(const float4*)(att + (size_t)ee[j] * HH);
                    const float2* xr = (const float2*)(g_x + (size_t)ss[j] * HC);
                    v[j][0] = xr[ 0 + lane];
                    v[j][1] = xr[32 + lane];
                    v[j][2] = xr[64 + lane];
                    v[j][3] = xr[96 + lane];
                }
            }
            #pragma unroll
            for (int j = 0; j < 4; j++) {
                if (j < nj) {
                    float a0 = ex[j].x * i0, a1 = ex[j].y * i1;
                    float a2 = ex[j].z * i2, a3 = ex[j].w * i3;
                    if (lane == 0)
                        *(float4*)(att + (size_t)ee[j] * HH) = make_float4(a0, a1, a2, a3);
                    acc0 = fmaf(a0, v[j][0].x, acc0); acc1 = fmaf(a0, v[j][0].y, acc1);
                    acc0 = fmaf(a1, v[j][1].x, acc0); acc1 = fmaf(a1, v[j][1].y, acc1);
                    acc0 = fmaf(a2, v[j][2].x, acc0); acc1 = fmaf(a2, v[j][2].y, acc1);
                    acc0 = fmaf(a3, v[j][3].x, acc0); acc1 = fmaf(a3, v[j][3].y, acc1);
                }
            }
        }
    }
    ((float2*)(outy + (size_t)n * CC))[lane] = make_float2(acc0, acc1);
}

// GraphNorm: one block per group (batch_ptr sorted -> contiguous node ranges).
__global__ void k_gn(const int* __restrict__ batch_ptr,
                     const float* __restrict__ bias,
                     const float* __restrict__ gnw,
                     const float* __restrict__ gnb,
                     const float* __restrict__ gnsc,
                     float* __restrict__ outy) {
    int g = blockIdx.x;
    __shared__ int s_lo, s_hi;
    if (threadIdx.x == 0) {
        int lo = 0, hi = NN;
        while (lo < hi) { int m = (lo + hi) >> 1; if (batch_ptr[m] < g) lo = m + 1; else hi = m; }
        s_lo = lo;
        int lo2 = lo, hi2 = NN;
        while (lo2 < hi2) { int m = (lo2 + hi2) >> 1; if (batch_ptr[m] < g + 1) lo2 = m + 1; else hi2 = m; }
        s_hi = lo2;
    }
    __syncthreads();
    int lo = s_lo, hi = s_hi;
    float cnt = (float)max(hi - lo, 1);
    int ch = threadIdx.x & 63;
    int ro = threadIdx.x >> 6;  // 0..3
    float b = bias[ch], w = gnw[ch], gb = gnb[ch], sc = gnsc[ch];
    __shared__ float red[256];
    __shared__ float s_ms[64], s_rs[64];

    float s = 0.0f;
    for (int r = lo + ro; r < hi; r += 4) s += outy[r * CC + ch];
    red[threadIdx.x] = s;
    __syncthreads();
    if (threadIdx.x < 64) {
        float m = red[threadIdx.x] + red[threadIdx.x + 64] + red[threadIdx.x + 128] + red[threadIdx.x + 192];
        float mean = 0.25f * m / cnt + b;
        s_ms[threadIdx.x] = mean * sc;
    }
    __syncthreads();
    float ms = s_ms[ch];

    s = 0.0f;
    for (int r = lo + ro; r < hi; r += 4) {
        float t = fmaf(outy[r * CC + ch], 0.25f, b) - ms;
        s += t * t;
    }
    red[threadIdx.x] = s;
    __syncthreads();
    if (threadIdx.x < 64) {
        float v = (red[threadIdx.x] + red[threadIdx.x + 64] + red[threadIdx.x + 128] + red[threadIdx.x + 192]) / cnt;
        s_rs[threadIdx.x] = rsqrtf(v + GN_EPS);
    }
    __syncthreads();
    float rs = s_rs[ch];

    for (int r = lo + ro; r < hi; r += 4) {
        float t = (fmaf(outy[r * CC + ch], 0.25f, b) - ms) * rs;
        float y = fmaf(w, t, gb);
        outy[r * CC + ch] = fmaxf(y, 0.0f);
    }
}

// ---------------- launch ----------------
extern "C" void kernel_launch(void* const* d_in, const int* in_sizes, int n_in,
                              void* d_out, int out_size) {
    const float* node      = (const float*)d_in[0];
    const int*   ei        = (const int*)d_in[1];
    const float* edge_attr = (const float*)d_in[2];
    const int*   batch_ptr = (const int*)d_in[3];
    const float* W         = (const float*)d_in[4];
    const float* W_edge    = (const float*)d_in[5];
    const float* att_src   = (const float*)d_in[6];
    const float* att_dst   = (const float*)d_in[7];
    const float* att_edge  = (const float*)d_in[8];
    const float* bias      = (const float*)d_in[9];
    const float* gnw       = (const float*)d_in[10];
    const float* gnb       = (const float*)d_in[11];
    const float* gnsc      = (const float*)d_in[12];

    float* outy = (float*)d_out;                    // y region [N*C]
    float* att  = (float*)d_out + (size_t)NN * CC;  // att region [E*H]

    k_init<<<256, 256>>>();
    k_vedge<<<1, 64>>>(W_edge, att_edge);
    k_proj<<<(NN + PROJ_ROWS - 1) / PROJ_ROWS, 256>>>(node, W, att_src, att_dst);
    k_edgeA<<<(EE + 255) / 256, 256>>>(ei, edge_attr, att);
    k_scanA<<<NB, 256>>>();
    k_scanB<<<1, 256>>>();
    k_scanC<<<NB, 256>>>();
    k_scatter<<<(EE + 255) / 256, 256>>>(ei);
    k_aggr<<<(NN * 32 + 255) / 256, 256>>>(ei, att, outy);
    k_gn<<<GG, 256>>>(batch_ptr, bias, gnw, gnb, gnsc, outy);
}

// round 15
// speedup vs baseline: 1.1810x; 1.1810x over previous
#include <cuda_runtime.h>
#include <cuda_fp16.h>
#include <math_constants.h>

#define NN 50000
#define EE 800000
#define HH 4
#define CC 64
#define DE 16
#define GG 64
#define HC 256   // H*C
#define NEG_SLOPE 0.2f
#define GN_EPS 1e-5f

// ---------------- device scratch (no allocations allowed) ----------------
__device__ __half g_xh[NN * HC];    // projected node features, fp16 [N, H*C] (25.6 MB)
__device__ float  g_asrc[NN * HH];  // per-node src attention logits (fp32)
__device__ float  g_adst[NN * HH];  // per-node dst attention logits (fp32)
__device__ float  g_denom[NN * HH]; // segment sum of exp per (dst, h)
__device__ float  g_vedge[DE * HH]; // folded W_edge @ att_edge, layout [d][h]

__device__ __forceinline__ void red_add_v4(float* p, float a, float b, float c, float d) {
    asm volatile("red.global.add.v4.f32 [%0], {%1, %2, %3, %4};"
                 :: "l"(p), "f"(a), "f"(b), "f"(c), "f"(d) : "memory");
}

// Convert 4 packed halves (loaded as float2 = 8B) to float4.
__device__ __forceinline__ float4 h4f(float2 raw) {
    __half2 lo = *(__half2*)&raw.x;
    __half2 hi = *(__half2*)&raw.y;
    float2 a = __half22float2(lo);
    float2 b = __half22float2(hi);
    return make_float4(a.x, a.y, b.x, b.y);
}

// ---------------- kernels ----------------

// Zero the y output region and softmax denominators.
__global__ void k_init(float* __restrict__ outy) {
    int i = blockIdx.x * blockDim.x + threadIdx.x;
    int stride = gridDim.x * blockDim.x;
    for (int j = i; j < NN * CC; j += stride) outy[j] = 0.0f;
    for (int j = i; j < NN * HH; j += stride) g_denom[j] = 0.0f;
}

// v[d][h] = sum_c W_edge[d, h*C + c] * att_edge[h, c]   (tiny: 16x4)
__global__ void k_vedge(const float* __restrict__ We, const float* __restrict__ ae) {
    int t = threadIdx.x;           // 64 threads
    int d = t >> 2, h = t & 3;
    float s = 0.0f;
    #pragma unroll 16
    for (int c = 0; c < CC; c++)
        s = fmaf(We[d * HC + h * CC + c], ae[h * CC + c], s);
    g_vedge[d * HH + h] = s;
}

// x = node @ W (stored fp16), fused with fp32 a_src/a_dst reduction.
#define PROJ_ROWS 32
__global__ void k_proj(const float* __restrict__ node, const float* __restrict__ W,
                       const float* __restrict__ att_src, const float* __restrict__ att_dst) {
    __shared__ float sn[PROJ_ROWS][CC];
    __shared__ float s_s[8][PROJ_ROWS];
    __shared__ float s_d[8][PROJ_ROWS];
    int block0 = blockIdx.x * PROJ_ROWS;
    int tid = threadIdx.x;  // 256
    for (int i = tid; i < PROJ_ROWS * CC; i += 256) {
        int r = i >> 6, c = i & 63;
        int n = block0 + r;
        sn[r][c] = (n < NN) ? node[n * CC + c] : 0.0f;
    }
    __syncthreads();
    float acc[PROJ_ROWS];
    #pragma unroll
    for (int r = 0; r < PROJ_ROWS; r++) acc[r] = 0.0f;
    #pragma unroll 4
    for (int k = 0; k < CC; k++) {
        float wk = W[k * HC + tid];
        #pragma unroll
        for (int r = 0; r < PROJ_ROWS; r++) acc[r] = fmaf(sn[r][k], wk, acc[r]);
    }
    float as = att_src[tid], ad = att_dst[tid];
    int warp = tid >> 5, lane = tid & 31;
    #pragma unroll
    for (int r = 0; r < PROJ_ROWS; r++) {
        int n = block0 + r;
        if (n < NN) g_xh[(size_t)n * HC + tid] = __float2half_rn(acc[r]);
        float ps = acc[r] * as;
        float pd = acc[r] * ad;
        #pragma unroll
        for (int o = 16; o > 0; o >>= 1) {
            ps += __shfl_xor_sync(0xffffffffu, ps, o);
            pd += __shfl_xor_sync(0xffffffffu, pd, o);
        }
        if (lane == 0) { s_s[warp][r] = ps; s_d[warp][r] = pd; }
    }
    __syncthreads();
    int r = tid & 31;
    int h = (tid >> 5) & 3;
    int which = tid >> 7;
    int n = block0 + r;
    if (n < NN) {
        if (which == 0) g_asrc[n * HH + h] = s_s[2 * h][r] + s_s[2 * h + 1][r];
        else            g_adst[n * HH + h] = s_d[2 * h][r] + s_d[2 * h + 1][r];
    }
}

// Edge pass: ex = exp(lrelu(a_src[src]+a_dst[dst]+edge_attr@v)) (no max needed:
// logits are O(10), far from fp32 overflow; ratio mathematically identical).
// Stores ex and accumulates the per-(dst,h) denominator with ONE v4 reduction.
__global__ void k_edgeA(const int* __restrict__ ei,
                        const float* __restrict__ edge_attr,
                        float* __restrict__ att) {
    __shared__ float sv[DE * HH];
    if (threadIdx.x < DE * HH) sv[threadIdx.x] = g_vedge[threadIdx.x];
    __syncthreads();
    int e = blockIdx.x * blockDim.x + threadIdx.x;
    if (e >= EE) return;
    const float4* ea = (const float4*)(edge_attr + (size_t)e * DE);
    float aeh[HH] = {0.f, 0.f, 0.f, 0.f};
    #pragma unroll
    for (int q = 0; q < 4; q++) {
        float4 t = ea[q];
        #pragma unroll
        for (int h = 0; h < HH; h++) {
            aeh[h] += t.x * sv[(q * 4 + 0) * HH + h]
                    + t.y * sv[(q * 4 + 1) * HH + h]
                    + t.z * sv[(q * 4 + 2) * HH + h]
                    + t.w * sv[(q * 4 + 3) * HH + h];
        }
    }
    int src = ei[e], dst = ei[EE + e];
    float4 s4 = *(const float4*)(g_asrc + src * HH);
    float4 d4 = *(const float4*)(g_adst + dst * HH);
    float a0 = s4.x + d4.x + aeh[0];
    float a1 = s4.y + d4.y + aeh[1];
    float a2 = s4.z + d4.z + aeh[2];
    float a3 = s4.w + d4.w + aeh[3];
    a0 = (a0 > 0.0f) ? a0 : NEG_SLOPE * a0;
    a1 = (a1 > 0.0f) ? a1 : NEG_SLOPE * a1;
    a2 = (a2 > 0.0f) ? a2 : NEG_SLOPE * a2;
    a3 = (a3 > 0.0f) ? a3 : NEG_SLOPE * a3;
    float e0 = __expf(a0), e1 = __expf(a1), e2 = __expf(a2), e3 = __expf(a3);
    *(float4*)(att + (size_t)e * HH) = make_float4(e0, e1, e2, e3);
    red_add_v4(&g_denom[dst * HH], e0, e1, e2, e3);
}

// Pass C: att = ex/denom (write output), scatter head-summed message into out[N,C].
// 16 lanes per edge; lane owns channels 4*lane..4*lane+3 -> four 8B fp16 loads
// (one per head) + ONE v4 RED per lane.
__global__ void k_edgeC(const int* __restrict__ ei,
                        float* __restrict__ att,
                        float* __restrict__ outy) {
    int t = blockIdx.x * blockDim.x + threadIdx.x;
    int e = t >> 4;
    int lane = threadIdx.x & 15;
    if (e >= EE) return;
    int src = ei[e], dst = ei[EE + e];
    float4 ex = *(const float4*)(att + (size_t)e * HH);
    float4 dn = *(const float4*)(g_denom + dst * HH);
    float a0 = ex.x / (dn.x + 1e-16f);
    float a1 = ex.y / (dn.y + 1e-16f);
    float a2 = ex.z / (dn.z + 1e-16f);
    float a3 = ex.w / (dn.w + 1e-16f);
    if (lane == 0)
        *(float4*)(att + (size_t)e * HH) = make_float4(a0, a1, a2, a3);
    // Row = 256 halves = 64 8-byte chunks; head h occupies chunks [16h, 16h+16).
    const float2* xr = (const float2*)(g_xh + (size_t)src * HC);
    float4 v0 = h4f(xr[ 0 + lane]);   // head 0, channels 4*lane..4*lane+3
    float4 v1 = h4f(xr[16 + lane]);   // head 1
    float4 v2 = h4f(xr[32 + lane]);   // head 2
    float4 v3 = h4f(xr[48 + lane]);   // head 3
    float r0 = fmaf(a0, v0.x, fmaf(a1, v1.x, fmaf(a2, v2.x, a3 * v3.x)));
    float r1 = fmaf(a0, v0.y, fmaf(a1, v1.y, fmaf(a2, v2.y, a3 * v3.y)));
    float r2 = fmaf(a0, v0.z, fmaf(a1, v1.z, fmaf(a2, v2.z, a3 * v3.z)));
    float r3 = fmaf(a0, v0.w, fmaf(a1, v1.w, fmaf(a2, v2.w, a3 * v3.w)));
    red_add_v4(outy + (size_t)dst * CC + lane * 4, r0, r1, r2, r3);
}

// GraphNorm: one block (512 thr) per group; fused sum/sumsq stats pass.
__global__ void k_gn(const int* __restrict__ batch_ptr,
                     const float* __restrict__ bias,
                     const float* __restrict__ gnw,
                     const float* __restrict__ gnb,
                     const float* __restrict__ gnsc,
                     float* __restrict__ outy) {
    int g = blockIdx.x;
    __shared__ int s_lo, s_hi;
    if (threadIdx.x == 0) {
        int lo = 0, hi = NN;
        while (lo < hi) { int m = (lo + hi) >> 1; if (batch_ptr[m] < g) lo = m + 1; else hi = m; }
        s_lo = lo;
        int lo2 = lo, hi2 = NN;
        while (lo2 < hi2) { int m = (lo2 + hi2) >> 1; if (batch_ptr[m] < g + 1) lo2 = m + 1; else hi2 = m; }
        s_hi = lo2;
    }
    __syncthreads();
    int lo = s_lo, hi = s_hi;
    float cnt = (float)max(hi - lo, 1);
    int ch = threadIdx.x & 63;
    int ro = threadIdx.x >> 6;  // 0..7
    float b = bias[ch], w = gnw[ch], gb = gnb[ch], sc = gnsc[ch];
    __shared__ float redS[512], redQ[512];
    __shared__ float s_ms[64], s_rs[64];

    // single stats pass: accumulate t and t^2, t = raw/4 + bias
    float s = 0.0f, q = 0.0f;
    for (int r = lo + ro; r < hi; r += 8) {
        float t = fmaf(outy[r * CC + ch], 0.25f, b);
        s += t;
        q = fmaf(t, t, q);
    }
    redS[threadIdx.x] = s;
    redQ[threadIdx.x] = q;
    __syncthreads();
    if (threadIdx.x < 64) {
        float S = 0.0f, Q = 0.0f;
        #pragma unroll
        for (int k = 0; k < 8; k++) {
            S += redS[threadIdx.x + 64 * k];
            Q += redQ[threadIdx.x + 64 * k];
        }
        float mean = S / cnt;
        float ms = mean * sc;
        // var of (t - ms): E[t^2] - 2*ms*mean + ms^2
        float var = Q / cnt - 2.0f * ms * mean + ms * ms;
        s_ms[threadIdx.x] = ms;
        s_rs[threadIdx.x] = rsqrtf(var + GN_EPS);
    }
    __syncthreads();
    float ms = s_ms[ch];
    float rs = s_rs[ch];

    // normalize + affine + relu (in place)
    for (int r = lo + ro; r < hi; r += 8) {
        float t = (fmaf(outy[r * CC + ch], 0.25f, b) - ms) * rs;
        float y = fmaf(w, t, gb);
        outy[r * CC + ch] = fmaxf(y, 0.0f);
    }
}

// ---------------- launch ----------------
extern "C" void kernel_launch(void* const* d_in, const int* in_sizes, int n_in,
                              void* d_out, int out_size) {
    const float* node      = (const float*)d_in[0];
    const int*   ei        = (const int*)d_in[1];
    const float* edge_attr = (const float*)d_in[2];
    const int*   batch_ptr = (const int*)d_in[3];
    const float* W         = (const float*)d_in[4];
    const float* W_edge    = (const float*)d_in[5];
    const float* att_src   = (const float*)d_in[6];
    const float* att_dst   = (const float*)d_in[7];
    const float* att_edge  = (const float*)d_in[8];
    const float* bias      = (const float*)d_in[9];
    const float* gnw       = (const float*)d_in[10];
    const float* gnb       = (const float*)d_in[11];
    const float* gnsc      = (const float*)d_in[12];

    float* outy = (float*)d_out;                    // y region [N*C]
    float* att  = (float*)d_out + (size_t)NN * CC;  // att region [E*H]

    k_init<<<1024, 256>>>(outy);
    k_vedge<<<1, 64>>>(W_edge, att_edge);
    k_proj<<<(NN + PROJ_ROWS - 1) / PROJ_ROWS, 256>>>(node, W, att_src, att_dst);
    k_edgeA<<<(EE + 255) / 256, 256>>>(ei, edge_attr, att);
    k_edgeC<<<(EE * 16 + 255) / 256, 256>>>(ei, att, outy);
    k_gn<<<GG, 512>>>(batch_ptr, bias, gnw, gnb, gnsc, outy);
}